// round 9
// baseline (speedup 1.0000x reference)
#include <cuda_runtime.h>

// Problem constants (fixed by the reference):
//   B=32768, LMAX=24, M=10, D=300, V=36
#define BB     32768
#define LMAXC  24
#define MC     10
#define D4C    75            // float4s per (b,m) row
#define ROW4   750           // float4s per batch element (10*75)
#define F4_PER_THREAD 4
#define F4_PER_BLOCK  1024   // 256 threads * 4

// Linear mapping: thread handles float4 indices base + s*256, s=0..3.
// Every warp store wavefront is 512B, 512B-aligned, fully dense.
__global__ __launch_bounds__(256)
void word_emb_kernel(const float4* __restrict__ emb,     // [36, 75] float4
                     const float4* __restrict__ pad,     // [75] float4
                     const int*    __restrict__ tokens,  // [B, 24]
                     const int*    __restrict__ lengths, // [B]
                     float4*       __restrict__ out)     // [B*10*75] float4
{
    const int base = blockIdx.x * F4_PER_BLOCK + threadIdx.x;

    float4 v[F4_PER_THREAD];

    #pragma unroll
    for (int s = 0; s < F4_PER_THREAD; s++) {
        const int i = base + s * 256;
        const int b = i / ROW4;
        const int r = i - b * ROW4;
        const int m = r / D4C;
        const int c = r - m * D4C;

        const int L = __ldg(lengths + b);
        const int* tok = tokens + b * LMAXC;

        // Flatten both branches into one lerp:
        //   interp (L>=10): lo/hi/w from pos = m*(L-1)/9
        //   in-word pad   (L<10, m<L): lo=hi=m, w=0  -> exact embedding
        //   pad vec       (L<10, m>=L): A=B=pad row, w=0 -> exact pad
        int   lo = m, hi = m;
        float w  = 0.0f;
        if (L >= MC) {
            const float pos = (float)(m * (L - 1)) / 9.0f;  // same fp32 path as ref
            lo = (int)pos;
            hi = min(lo + 1, L - 1);
            w  = pos - (float)lo;
        }
        const bool usepad = (L < MC) & (m >= L);

        const float4* A;
        const float4* Bp;
        if (usepad) {
            A  = pad + c;
            Bp = pad + c;
        } else {
            A  = emb + __ldg(tok + lo) * D4C + c;
            Bp = emb + __ldg(tok + hi) * D4C + c;
        }
        const float4 a  = __ldg(A);
        const float4 bb = __ldg(Bp);
        const float  n  = 1.0f - w;

        v[s].x = a.x * n + bb.x * w;
        v[s].y = a.y * n + bb.y * w;
        v[s].z = a.z * n + bb.z * w;
        v[s].w = a.w * n + bb.w * w;
    }

    #pragma unroll
    for (int s = 0; s < F4_PER_THREAD; s++) {
        __stcs(out + base + s * 256, v[s]);
    }
}

extern "C" void kernel_launch(void* const* d_in, const int* in_sizes, int n_in,
                              void* d_out, int out_size)
{
    const float4* emb     = (const float4*)d_in[0];  // emb_table [36, 300] f32
    const float4* pad     = (const float4*)d_in[1];  // pad_table [1, 300] f32
    const int*    tokens  = (const int*)d_in[2];     // tokens [32768, 24] i32
    const int*    lengths = (const int*)d_in[3];     // lengths [32768] i32
    float4*       out     = (float4*)d_out;          // [32768, 10, 300] f32

    const int total4 = BB * ROW4;                    // 24,576,000 float4
    const int blocks = total4 / F4_PER_BLOCK;        // 24,000 (exact)
    word_emb_kernel<<<blocks, 256>>>(emb, pad, tokens, lengths, out);
}